// round 1
// baseline (speedup 1.0000x reference)
#include <cuda_runtime.h>
#include <math.h>

// Problem constants (fixed by reference setup_inputs)
#define B_  8
#define C_  512
#define T_  4096
#define O_  512
#define CK_ 1536          // C*K, K=3
#define EPS 1e-8f

// Scratch (device globals; allocation-free per harness rules)
__device__ float g_n2[B_ * T_];          // ||e(:,t)||^2
__device__ float g_d [B_ * T_];          // dot(e(:,t), e(:,t-1)), 0 at t=0
__device__ float g_s [B_ * 3 * T_];      // s0, s1, s2 per (b,t)

// ---------------------------------------------------------------------------
// Kernel 1: per-(b,t) column stats of embedding.
// grid (T/256, B), block 256. Coalesced: per c-iteration a warp reads 32
// consecutive t's.
// ---------------------------------------------------------------------------
__global__ void sim_stats_kernel(const float* __restrict__ emb) {
    const int t = blockIdx.x * 256 + threadIdx.x;
    const int b = blockIdx.y;
    const float* e = emb + (size_t)b * C_ * T_ + t;

    float n2 = 0.f, dd = 0.f;
    if (t > 0) {
        #pragma unroll 4
        for (int c = 0; c < C_; ++c) {
            float v  = e[(size_t)c * T_];
            float vp = e[(size_t)c * T_ - 1];
            n2 = fmaf(v, v,  n2);
            dd = fmaf(v, vp, dd);
        }
    } else {
        #pragma unroll 4
        for (int c = 0; c < C_; ++c) {
            float v = e[(size_t)c * T_];
            n2 = fmaf(v, v, n2);
        }
    }
    g_n2[b * T_ + t] = n2;
    g_d [b * T_ + t] = dd;
}

// ---------------------------------------------------------------------------
// Kernel 2: finalize the three cosine similarities with torch eps semantics.
// ---------------------------------------------------------------------------
__global__ void sim_finalize_kernel() {
    const int idx = blockIdx.x * 256 + threadIdx.x;
    if (idx >= B_ * T_) return;
    const int b = idx / T_;
    const int t = idx - b * T_;
    const float* n2 = g_n2 + b * T_;
    const float* d  = g_d  + b * T_;

    float nm    = fmaxf(sqrtf(n2[t]), EPS);
    float nprev = (t > 0)      ? fmaxf(sqrtf(n2[t - 1]), EPS) : EPS;
    float nnext = (t < T_ - 1) ? fmaxf(sqrtf(n2[t + 1]), EPS) : EPS;

    float s0 = d[t] / (nm * nprev);                       // d[0] == 0 -> s0(0)=0
    float s1 = n2[t] / (nm * nm);
    float s2 = ((t < T_ - 1) ? d[t + 1] : 0.f) / (nm * nnext);

    float* s = g_s + (size_t)b * 3 * T_;
    s[0 * T_ + t] = s0;
    s[1 * T_ + t] = s1;
    s[2 * T_ + t] = s2;
}

// ---------------------------------------------------------------------------
// Kernel 3: per-batch GEMM  out[b] = W[O, CK] x Xs[CK, T]
//   Xs[i, t] = feature[b, i/3, t + i%3 - 1] * s[b, i>>9, t]
// Group g = i>>9 is uniform within each BK=8 chunk (512 % 8 == 0), so the
// scale is folded into the shared-memory im2col fill.
// Block tile 128x128, K-step 8, 256 threads, 8x8 per-thread micro-tile.
// ---------------------------------------------------------------------------
#define BM 128
#define BN 128
#define BK 8
#define TM 8
#define TN 8

__global__ __launch_bounds__(256, 2)
void attconv_gemm_kernel(const float* __restrict__ feat,
                         const float* __restrict__ w,
                         float* __restrict__ out) {
    __shared__ float sW[BK][BM];
    __shared__ float sX[BK][BN];
    __shared__ float sS[3][BN];

    const int b     = blockIdx.z;
    const int mBase = blockIdx.y * BM;     // over O
    const int nBase = blockIdx.x * BN;     // over T
    const int tid   = threadIdx.x;

    const float* fb = feat + (size_t)b * C_ * T_;
    const float* sb = g_s  + (size_t)b * 3 * T_;

    // preload scale rows for this n-tile
    for (int i = tid; i < 3 * BN; i += 256) {
        int g = i / BN, col = i - g * BN;
        sS[g][col] = sb[g * T_ + nBase + col];
    }

    // compute-thread mapping
    const int ty = tid >> 4;               // 0..15 -> m micro-tile
    const int tx = tid & 15;               // 0..15 -> n micro-tile
    // W fill mapping: one float4 per thread
    const int wRow = tid >> 1;             // 0..127
    const int wCol = (tid & 1) * 4;        // 0 or 4
    // X fill mapping: one warp per row, 4 scalars per thread
    const int xRow = tid >> 5;             // 0..7
    const int xCol = (tid & 31) * 4;       // 0..124

    float acc[TM][TN] = {};
    float sreg[4];
    int curG = -1;

    __syncthreads();   // sS visible

    for (int iBase = 0; iBase < CK_; iBase += BK) {
        const int g = iBase >> 9;
        if (g != curG) {
            curG = g;
            sreg[0] = sS[g][xCol + 0];
            sreg[1] = sS[g][xCol + 1];
            sreg[2] = sS[g][xCol + 2];
            sreg[3] = sS[g][xCol + 3];
        }

        // ---- stage global -> registers ----
        float4 wv = *reinterpret_cast<const float4*>(
            &w[(size_t)(mBase + wRow) * CK_ + iBase + wCol]);

        const int irow = iBase + xRow;
        const int c    = irow / 3;
        const int k    = irow - c * 3;
        const float* fr = fb + (size_t)c * T_;
        const int t0 = nBase + xCol + k - 1;
        float xv[4];
        #pragma unroll
        for (int j = 0; j < 4; ++j) {
            int tt = t0 + j;
            xv[j] = (tt >= 0 && tt < T_) ? fr[tt] : 0.f;
        }

        __syncthreads();   // previous compute done

        // ---- registers -> shared ----
        sW[wCol + 0][wRow] = wv.x;
        sW[wCol + 1][wRow] = wv.y;
        sW[wCol + 2][wRow] = wv.z;
        sW[wCol + 3][wRow] = wv.w;
        #pragma unroll
        for (int j = 0; j < 4; ++j)
            sX[xRow][xCol + j] = xv[j] * sreg[j];

        __syncthreads();   // tile ready

        // ---- compute ----
        #pragma unroll
        for (int kk = 0; kk < BK; ++kk) {
            const float4* ap = reinterpret_cast<const float4*>(&sW[kk][ty * TM]);
            const float4* bp = reinterpret_cast<const float4*>(&sX[kk][tx * TN]);
            float4 a0 = ap[0], a1 = ap[1];
            float4 b0 = bp[0], b1 = bp[1];
            float av[TM] = {a0.x, a0.y, a0.z, a0.w, a1.x, a1.y, a1.z, a1.w};
            float bv[TN] = {b0.x, b0.y, b0.z, b0.w, b1.x, b1.y, b1.z, b1.w};
            #pragma unroll
            for (int mi = 0; mi < TM; ++mi)
                #pragma unroll
                for (int ni = 0; ni < TN; ++ni)
                    acc[mi][ni] = fmaf(av[mi], bv[ni], acc[mi][ni]);
        }
    }

    // ---- epilogue ----
    float* ob = out + (size_t)b * O_ * T_ + (size_t)(mBase + ty * TM) * T_
              + nBase + tx * TN;
    #pragma unroll
    for (int mi = 0; mi < TM; ++mi) {
        float4 v0 = make_float4(acc[mi][0], acc[mi][1], acc[mi][2], acc[mi][3]);
        float4 v1 = make_float4(acc[mi][4], acc[mi][5], acc[mi][6], acc[mi][7]);
        *reinterpret_cast<float4*>(&ob[(size_t)mi * T_ + 0]) = v0;
        *reinterpret_cast<float4*>(&ob[(size_t)mi * T_ + 4]) = v1;
    }
}

// ---------------------------------------------------------------------------
// Launch: inputs in metadata order: feature, embedding, weight
// ---------------------------------------------------------------------------
extern "C" void kernel_launch(void* const* d_in, const int* in_sizes, int n_in,
                              void* d_out, int out_size) {
    const float* feature   = (const float*)d_in[0];
    const float* embedding = (const float*)d_in[1];
    const float* weight    = (const float*)d_in[2];
    float* out = (float*)d_out;

    sim_stats_kernel<<<dim3(T_ / 256, B_), 256>>>(embedding);
    sim_finalize_kernel<<<(B_ * T_ + 255) / 256, 256>>>();
    attconv_gemm_kernel<<<dim3(T_ / BN, O_ / BM, B_), 256>>>(feature, weight, out);
}

// round 3
// speedup vs baseline: 3.1710x; 3.1710x over previous
#include <cuda_runtime.h>
#include <math.h>
#include <cstdint>

// Problem constants
#define B_  8
#define C_  512
#define T_  4096
#define O_  512
#define CK_ 1536
#define EPS 1e-8f

// GEMM tiling
#define BM 128
#define BN 128
#define BK 32
#define NKT (CK_ / BK)        // 48
#define THREADS 256

// SMEM layout in uint32 units (padded stride 36 for bank-conflict-free frags)
#define ROWSTRIDE 36
#define TILE_U32  (128 * ROWSTRIDE)     // 4608
#define OFF_SS    0                     // 3*128 floats scales
#define OFF_A     384                   // 2 stages
#define OFF_B     (384 + 2 * TILE_U32)
#define SMEM_U32  (384 + 4 * TILE_U32)  // 18816 u32 = 75264 B

// Scratch
__device__ float g_n2[B_ * T_];
__device__ float g_d [B_ * T_];
__device__ float g_s [B_ * 3 * T_];

__device__ __forceinline__ uint32_t f2tf32(float f) {
    uint32_t r;
    asm("cvt.rna.tf32.f32 %0, %1;" : "=r"(r) : "f"(f));
    return r;
}

__device__ __forceinline__ void mma_m16n8k8(float* d, const uint32_t* a,
                                            const uint32_t* b) {
    asm volatile(
        "mma.sync.aligned.m16n8k8.row.col.f32.tf32.tf32.f32 "
        "{%0,%1,%2,%3}, {%4,%5,%6,%7}, {%8,%9}, {%0,%1,%2,%3};"
        : "+f"(d[0]), "+f"(d[1]), "+f"(d[2]), "+f"(d[3])
        : "r"(a[0]), "r"(a[1]), "r"(a[2]), "r"(a[3]), "r"(b[0]), "r"(b[1]));
}

// ---------------------------------------------------------------------------
// Kernel 1: column stats. grid (T/64, B), block 256, C split 4-way.
// ---------------------------------------------------------------------------
__global__ void sim_stats_kernel(const float* __restrict__ emb) {
    const int tsub = threadIdx.x & 63;
    const int cp   = threadIdx.x >> 6;
    const int t    = blockIdx.x * 64 + tsub;
    const int b    = blockIdx.y;
    const float* e = emb + (size_t)b * C_ * T_ + (size_t)cp * 128 * T_ + t;

    float n2 = 0.f, dd = 0.f;
    if (t > 0) {
        #pragma unroll 4
        for (int c = 0; c < 128; ++c) {
            float v  = e[(size_t)c * T_];
            float vp = e[(size_t)c * T_ - 1];
            n2 = fmaf(v, v,  n2);
            dd = fmaf(v, vp, dd);
        }
    } else {
        #pragma unroll 4
        for (int c = 0; c < 128; ++c) {
            float v = e[(size_t)c * T_];
            n2 = fmaf(v, v, n2);
        }
    }
    __shared__ float sn[4][64], sd[4][64];
    sn[cp][tsub] = n2;
    sd[cp][tsub] = dd;
    __syncthreads();
    if (threadIdx.x < 64) {
        g_n2[b * T_ + t] = sn[0][tsub] + sn[1][tsub] + sn[2][tsub] + sn[3][tsub];
        g_d [b * T_ + t] = sd[0][tsub] + sd[1][tsub] + sd[2][tsub] + sd[3][tsub];
    }
}

// ---------------------------------------------------------------------------
// Kernel 2: finalize cosine sims (torch eps semantics).
// ---------------------------------------------------------------------------
__global__ void sim_finalize_kernel() {
    const int idx = blockIdx.x * 256 + threadIdx.x;
    if (idx >= B_ * T_) return;
    const int b = idx / T_;
    const int t = idx - b * T_;
    const float* n2 = g_n2 + b * T_;
    const float* d  = g_d  + b * T_;

    float nm    = fmaxf(sqrtf(n2[t]), EPS);
    float nprev = (t > 0)      ? fmaxf(sqrtf(n2[t - 1]), EPS) : EPS;
    float nnext = (t < T_ - 1) ? fmaxf(sqrtf(n2[t + 1]), EPS) : EPS;

    float* s = g_s + (size_t)b * 3 * T_;
    s[0 * T_ + t] = d[t] / (nm * nprev);
    s[1 * T_ + t] = n2[t] / (nm * nm);
    s[2 * T_ + t] = ((t < T_ - 1) ? d[t + 1] : 0.f) / (nm * nnext);
}

// ---------------------------------------------------------------------------
// Kernel 3: tf32 mma.sync GEMM.  out[b] = W[O,CK] x Xs[CK,T]
//   Xs[i,t] = feature[b, i/3, t + i%3 - 1] * s[b, i>>9, t]
// CTA 128x128x32 double-buffered; warp grid 4(m) x 2(n), warp tile 32x64.
// ---------------------------------------------------------------------------
__global__ __launch_bounds__(THREADS)
void attconv_gemm_mma(const float* __restrict__ feat,
                      const float* __restrict__ w,
                      float* __restrict__ out) {
    extern __shared__ uint32_t smem[];
    uint32_t* smA = smem + OFF_A;
    uint32_t* smB = smem + OFF_B;
    float*    sS  = (float*)(smem + OFF_SS);

    const int tid  = threadIdx.x;
    const int wid  = tid >> 5;
    const int lane = tid & 31;
    const int wm   = wid & 3;             // warp m index (0..3) -> 32 rows
    const int wn   = wid >> 2;            // warp n index (0..1) -> 64 cols
    const int b     = blockIdx.z;
    const int mBase = blockIdx.y * BM;
    const int nBase = blockIdx.x * BN;

    const float* fb   = feat + (size_t)b * C_ * T_;
    float*       outb = out  + (size_t)b * O_ * T_;

    // scale preload
    {
        const float* sbase = g_s + (size_t)b * 3 * T_;
        for (int i = tid; i < 3 * BN; i += THREADS) {
            int g = i >> 7, col = i & (BN - 1);
            sS[g * BN + col] = sbase[g * T_ + nBase + col];
        }
    }
    __syncthreads();

    // per-thread fixed mappings
    const int aRow  = tid >> 1;                 // 0..127 (W row in tile)
    const int aOff  = (tid & 1) * 16;           // k offset 0/16
    const int bCol  = tid & 127;                // Xs column in tile
    const int bHalf = (tid >> 7) * 16;          // k offset 0/16
    const float sc0 = sS[0 * BN + bCol];
    const float sc1 = sS[1 * BN + bCol];
    const float sc2 = sS[2 * BN + bCol];
    const float* wrow = w + (size_t)(mBase + aRow) * CK_ + aOff;

    uint32_t ra[16], rb[16];

    auto loadA = [&](int iBase) {
        #pragma unroll
        for (int j = 0; j < 16; j += 4) {
            float4 v = *reinterpret_cast<const float4*>(wrow + iBase + j);
            ra[j]   = f2tf32(v.x); ra[j+1] = f2tf32(v.y);
            ra[j+2] = f2tf32(v.z); ra[j+3] = f2tf32(v.w);
        }
    };
    auto loadB = [&](int iBase) {
        const int g = iBase >> 9;
        const float sg = (g == 0) ? sc0 : (g == 1) ? sc1 : sc2;
        const int i0 = iBase + bHalf;
        #pragma unroll
        for (int kk = 0; kk < 16; ++kk) {
            int i  = i0 + kk;
            int c  = i / 3;
            int k3 = i - 3 * c;
            int t  = nBase + bCol + k3 - 1;
            float v = ((unsigned)t < (unsigned)T_) ? fb[(size_t)c * T_ + t] : 0.f;
            rb[kk] = f2tf32(v * sg);
        }
    };
    auto storeTile = [&](int stage) {
        uint32_t* da = smA + stage * TILE_U32 + aRow * ROWSTRIDE + aOff;
        #pragma unroll
        for (int j = 0; j < 16; j += 4)
            *reinterpret_cast<uint4*>(da + j) =
                make_uint4(ra[j], ra[j+1], ra[j+2], ra[j+3]);
        uint32_t* db = smB + stage * TILE_U32 + bCol * ROWSTRIDE + bHalf;
        #pragma unroll
        for (int j = 0; j < 16; j += 4)
            *reinterpret_cast<uint4*>(db + j) =
                make_uint4(rb[j], rb[j+1], rb[j+2], rb[j+3]);
    };

    float acc[2][8][4] = {};

    // fragment SMEM base addresses (conflict-free: (4*(l/4)+l%4) spans 32 banks)
    const uint32_t* aFrag = smA + (wm * 32 + (lane >> 2)) * ROWSTRIDE + (lane & 3);
    const uint32_t* bFrag = smB + (wn * 64 + (lane >> 2)) * ROWSTRIDE + (lane & 3);

    auto compute = [&](int stage) {
        const uint32_t* ap = aFrag + stage * TILE_U32;
        const uint32_t* bp = bFrag + stage * TILE_U32;
        #pragma unroll
        for (int ks = 0; ks < 4; ++ks) {
            const int kk = ks * 8;
            uint32_t af[2][4];
            #pragma unroll
            for (int mi = 0; mi < 2; ++mi) {
                const uint32_t* p = ap + mi * 16 * ROWSTRIDE + kk;
                af[mi][0] = p[0];
                af[mi][1] = p[8 * ROWSTRIDE];
                af[mi][2] = p[4];
                af[mi][3] = p[8 * ROWSTRIDE + 4];
            }
            uint32_t bf[8][2];
            #pragma unroll
            for (int ni = 0; ni < 8; ++ni) {
                const uint32_t* p = bp + ni * 8 * ROWSTRIDE + kk;
                bf[ni][0] = p[0];
                bf[ni][1] = p[4];
            }
            #pragma unroll
            for (int mi = 0; mi < 2; ++mi)
                #pragma unroll
                for (int ni = 0; ni < 8; ++ni)
                    mma_m16n8k8(acc[mi][ni], af[mi], bf[ni]);
        }
    };

    // prologue
    loadA(0); loadB(0);
    storeTile(0);
    __syncthreads();

    for (int kt = 0; kt < NKT; ++kt) {
        const int cur = kt & 1;
        if (kt + 1 < NKT) { loadA((kt + 1) * BK); loadB((kt + 1) * BK); }
        compute(cur);
        if (kt + 1 < NKT) storeTile(cur ^ 1);
        __syncthreads();
    }

    // epilogue: direct float2 stores (64B per 8-lane group)
    const int rBase = mBase + wm * 32 + (lane >> 2);
    const int cBase = nBase + wn * 64 + (lane & 3) * 2;
    #pragma unroll
    for (int mi = 0; mi < 2; ++mi) {
        #pragma unroll
        for (int ni = 0; ni < 8; ++ni) {
            const int row = rBase + mi * 16;
            const int col = cBase + ni * 8;
            float2 v0 = make_float2(acc[mi][ni][0], acc[mi][ni][1]);
            float2 v1 = make_float2(acc[mi][ni][2], acc[mi][ni][3]);
            *reinterpret_cast<float2*>(&outb[(size_t)row * T_ + col])       = v0;
            *reinterpret_cast<float2*>(&outb[(size_t)(row + 8) * T_ + col]) = v1;
        }
    }
}

// ---------------------------------------------------------------------------
// Launch: inputs in metadata order: feature, embedding, weight
// ---------------------------------------------------------------------------
extern "C" void kernel_launch(void* const* d_in, const int* in_sizes, int n_in,
                              void* d_out, int out_size) {
    const float* feature   = (const float*)d_in[0];
    const float* embedding = (const float*)d_in[1];
    const float* weight    = (const float*)d_in[2];
    float* out = (float*)d_out;

    cudaFuncSetAttribute(attconv_gemm_mma,
                         cudaFuncAttributeMaxDynamicSharedMemorySize,
                         SMEM_U32 * 4);

    sim_stats_kernel<<<dim3(T_ / 64, B_), 256>>>(embedding);
    sim_finalize_kernel<<<(B_ * T_ + 255) / 256, 256>>>();
    attconv_gemm_mma<<<dim3(T_ / BN, O_ / BM, B_), THREADS, SMEM_U32 * 4>>>(
        feature, weight, out);
}

// round 4
// speedup vs baseline: 3.5490x; 1.1192x over previous
#include <cuda_runtime.h>
#include <math.h>
#include <cstdint>

// Problem constants
#define B_  8
#define C_  512
#define T_  4096
#define O_  512
#define CK_ 1536
#define EPS 1e-8f

// GEMM tiling
#define BM 128
#define BN 128
#define BK 32
#define NKT (CK_ / BK)        // 48
#define NKSG (CK_ / 8)        // 192 global k-steps
#define THREADS 256

// SMEM (u32 units): scales + 2-stage fragment-order B tile
#define BTILE_U32 4096                  // 4 ksteps * 16 n8 * 32 lanes * 2
#define OFF_SS    0
#define OFF_B     384
#define SMEM_U32  (384 + 2 * BTILE_U32) // 8576 u32 = 34304 B

// Scratch
__device__ float g_n2[B_ * T_];
__device__ float g_d [B_ * T_];
__device__ float g_s [B_ * 3 * T_];
__device__ uint4 g_wf[NKSG * 32 * 32];   // W repacked in fragment order (tf32)

__device__ __forceinline__ uint32_t f2tf32(float f) {
    uint32_t r;
    asm("cvt.rna.tf32.f32 %0, %1;" : "=r"(r) : "f"(f));
    return r;
}

__device__ __forceinline__ void mma_m16n8k8(float* d, const uint32_t* a,
                                            const uint32_t* b) {
    asm volatile(
        "mma.sync.aligned.m16n8k8.row.col.f32.tf32.tf32.f32 "
        "{%0,%1,%2,%3}, {%4,%5,%6,%7}, {%8,%9}, {%0,%1,%2,%3};"
        : "+f"(d[0]), "+f"(d[1]), "+f"(d[2]), "+f"(d[3])
        : "r"(a[0]), "r"(a[1]), "r"(a[2]), "r"(a[3]), "r"(b[0]), "r"(b[1]));
}

// ---------------------------------------------------------------------------
// Kernel 0: repack W [O, CK] -> fragment-major tf32.
// Output uint4 index: (ksg*32 + m16)*32 + lane.
//   x: W[m16*16 + lane/4,     ksg*8 + lane%4    ]
//   y: W[m16*16 + lane/4 + 8, ksg*8 + lane%4    ]
//   z: W[m16*16 + lane/4,     ksg*8 + lane%4 + 4]
//   w: W[m16*16 + lane/4 + 8, ksg*8 + lane%4 + 4]
// ---------------------------------------------------------------------------
__global__ void repack_w_kernel(const float* __restrict__ w) {
    const int idx  = blockIdx.x * 256 + threadIdx.x;   // 0 .. 192*32*32-1
    const int lane = idx & 31;
    const int m16  = (idx >> 5) & 31;
    const int ksg  = idx >> 10;
    const int row  = m16 * 16 + (lane >> 2);
    const int k    = ksg * 8 + (lane & 3);
    const float* p = w + (size_t)row * CK_ + k;
    uint4 v;
    v.x = f2tf32(p[0]);
    v.y = f2tf32(p[8 * CK_]);
    v.z = f2tf32(p[4]);
    v.w = f2tf32(p[8 * CK_ + 4]);
    g_wf[idx] = v;
}

// ---------------------------------------------------------------------------
// Kernel 1: column stats. grid (T/64, B), block 256, C split 4-way.
// ---------------------------------------------------------------------------
__global__ void sim_stats_kernel(const float* __restrict__ emb) {
    const int tsub = threadIdx.x & 63;
    const int cp   = threadIdx.x >> 6;
    const int t    = blockIdx.x * 64 + tsub;
    const int b    = blockIdx.y;
    const float* e = emb + (size_t)b * C_ * T_ + (size_t)cp * 128 * T_ + t;

    float n2 = 0.f, dd = 0.f;
    if (t > 0) {
        #pragma unroll 4
        for (int c = 0; c < 128; ++c) {
            float v  = e[(size_t)c * T_];
            float vp = e[(size_t)c * T_ - 1];
            n2 = fmaf(v, v,  n2);
            dd = fmaf(v, vp, dd);
        }
    } else {
        #pragma unroll 4
        for (int c = 0; c < 128; ++c) {
            float v = e[(size_t)c * T_];
            n2 = fmaf(v, v, n2);
        }
    }
    __shared__ float sn[4][64], sd[4][64];
    sn[cp][tsub] = n2;
    sd[cp][tsub] = dd;
    __syncthreads();
    if (threadIdx.x < 64) {
        g_n2[b * T_ + t] = sn[0][tsub] + sn[1][tsub] + sn[2][tsub] + sn[3][tsub];
        g_d [b * T_ + t] = sd[0][tsub] + sd[1][tsub] + sd[2][tsub] + sd[3][tsub];
    }
}

// ---------------------------------------------------------------------------
// Kernel 2: finalize cosine sims (torch eps semantics).
// ---------------------------------------------------------------------------
__global__ void sim_finalize_kernel() {
    const int idx = blockIdx.x * 256 + threadIdx.x;
    if (idx >= B_ * T_) return;
    const int b = idx / T_;
    const int t = idx - b * T_;
    const float* n2 = g_n2 + b * T_;
    const float* d  = g_d  + b * T_;

    float nm    = fmaxf(sqrtf(n2[t]), EPS);
    float nprev = (t > 0)      ? fmaxf(sqrtf(n2[t - 1]), EPS) : EPS;
    float nnext = (t < T_ - 1) ? fmaxf(sqrtf(n2[t + 1]), EPS) : EPS;

    float* s = g_s + (size_t)b * 3 * T_;
    s[0 * T_ + t] = d[t] / (nm * nprev);
    s[1 * T_ + t] = n2[t] / (nm * nm);
    s[2 * T_ + t] = ((t < T_ - 1) ? d[t + 1] : 0.f) / (nm * nnext);
}

// ---------------------------------------------------------------------------
// Kernel 3: tf32 mma GEMM, A frags from repacked global, B tile in SMEM
// stored directly in fragment order.
//   B frag layout idx(col,k) = ((ks*16 + col/8)*32 + 4*(col%8) + (k%4))*2
//                              + ((k%8)/4),   ks = k/8
// ---------------------------------------------------------------------------
__global__ __launch_bounds__(THREADS, 2)
void attconv_gemm_mma(const float* __restrict__ feat,
                      float* __restrict__ out) {
    extern __shared__ uint32_t smem[];
    float*    sS  = (float*)(smem + OFF_SS);
    uint32_t* smB = smem + OFF_B;

    const int tid  = threadIdx.x;
    const int wid  = tid >> 5;
    const int lane = tid & 31;
    const int wm   = wid & 3;             // warp m index -> 32 rows
    const int wn   = wid >> 2;            // warp n index -> 64 cols
    const int b     = blockIdx.z;
    const int mBase = blockIdx.y * BM;
    const int nBase = blockIdx.x * BN;

    const float* fb   = feat + (size_t)b * C_ * T_;
    float*       outb = out  + (size_t)b * O_ * T_;

    // scale preload
    {
        const float* sbase = g_s + (size_t)b * 3 * T_;
        for (int i = tid; i < 3 * BN; i += THREADS) {
            int g = i >> 7, col = i & (BN - 1);
            sS[g * BN + col] = sbase[g * T_ + nBase + col];
        }
    }
    __syncthreads();

    // B builder mapping
    const int bCol  = tid & 127;           // tile column (t)
    const int bHalf = (tid >> 7) * 16;     // k offset 0/16
    const float sc0 = sS[0 * BN + bCol];
    const float sc1 = sS[1 * BN + bCol];
    const float sc2 = sS[2 * BN + bCol];

    uint32_t rb[16];
    auto loadB = [&](int iBase) {
        const int g = iBase >> 9;
        const float sg = (g == 0) ? sc0 : (g == 1) ? sc1 : sc2;
        const int i0 = iBase + bHalf;
        #pragma unroll
        for (int kk = 0; kk < 16; ++kk) {
            int i  = i0 + kk;
            int c  = i / 3;
            int k3 = i - 3 * c;
            int t  = nBase + bCol + k3 - 1;
            float v = ((unsigned)t < (unsigned)T_) ? __ldg(&fb[(size_t)c * T_ + t]) : 0.f;
            rb[kk] = f2tf32(v * sg);
        }
    };
    // store in fragment order: per ks-half, 8 contiguous u32
    const int n8    = bCol >> 3;
    const int laneP = 4 * (bCol & 7);
    auto storeB = [&](int stage) {
        uint32_t* base = smB + stage * BTILE_U32;
        #pragma unroll
        for (int p = 0; p < 2; ++p) {
            const int ks = (bHalf >> 3) + p;
            uint32_t* d = base + ((ks * 16 + n8) * 32 + laneP) * 2;
            const int o = p * 8;
            *reinterpret_cast<uint4*>(d) =
                make_uint4(rb[o], rb[o + 4], rb[o + 1], rb[o + 5]);
            *reinterpret_cast<uint4*>(d + 4) =
                make_uint4(rb[o + 2], rb[o + 6], rb[o + 3], rb[o + 7]);
        }
    };

    float acc[2][8][4] = {};
    // A fragment pointers: g_wf[(ksg*32 + m16)*32 + lane]
    const int m16base = (mBase >> 4) + wm * 2;
    const uint4* aBase = g_wf + (size_t)m16base * 32 + lane;

    auto compute = [&](int stage, int kt) {
        const uint32_t* bp = smB + stage * BTILE_U32 + (wn * 8) * 32 * 2 + lane * 2;
        #pragma unroll
        for (int ks = 0; ks < 4; ++ks) {
            const int ksg = kt * 4 + ks;
            uint4 a0 = __ldg(aBase + ((size_t)ksg * 32 + 0) * 32);
            uint4 a1 = __ldg(aBase + ((size_t)ksg * 32 + 1) * 32);
            uint32_t af[2][4] = {{a0.x, a0.y, a0.z, a0.w},
                                 {a1.x, a1.y, a1.z, a1.w}};
            uint32_t bf[8][2];
            #pragma unroll
            for (int ni = 0; ni < 8; ++ni) {
                uint2 v = *reinterpret_cast<const uint2*>(
                    bp + (ks * 16 + ni) * 64);
                bf[ni][0] = v.x;
                bf[ni][1] = v.y;
            }
            #pragma unroll
            for (int mi = 0; mi < 2; ++mi)
                #pragma unroll
                for (int ni = 0; ni < 8; ++ni)
                    mma_m16n8k8(acc[mi][ni], af[mi], bf[ni]);
        }
    };

    // prologue
    loadB(0);
    storeB(0);
    __syncthreads();

    for (int kt = 0; kt < NKT; ++kt) {
        const int cur = kt & 1;
        if (kt + 1 < NKT) loadB((kt + 1) * BK);
        compute(cur, kt);
        if (kt + 1 < NKT) storeB(cur ^ 1);
        __syncthreads();
    }

    // epilogue: direct float2 stores
    const int rBase = mBase + wm * 32 + (lane >> 2);
    const int cBase = nBase + wn * 64 + (lane & 3) * 2;
    #pragma unroll
    for (int mi = 0; mi < 2; ++mi) {
        #pragma unroll
        for (int ni = 0; ni < 8; ++ni) {
            const int row = rBase + mi * 16;
            const int col = cBase + ni * 8;
            float2 v0 = make_float2(acc[mi][ni][0], acc[mi][ni][1]);
            float2 v1 = make_float2(acc[mi][ni][2], acc[mi][ni][3]);
            *reinterpret_cast<float2*>(&outb[(size_t)row * T_ + col])       = v0;
            *reinterpret_cast<float2*>(&outb[(size_t)(row + 8) * T_ + col]) = v1;
        }
    }
}

// ---------------------------------------------------------------------------
// Launch: inputs in metadata order: feature, embedding, weight
// ---------------------------------------------------------------------------
extern "C" void kernel_launch(void* const* d_in, const int* in_sizes, int n_in,
                              void* d_out, int out_size) {
    const float* feature   = (const float*)d_in[0];
    const float* embedding = (const float*)d_in[1];
    const float* weight    = (const float*)d_in[2];
    float* out = (float*)d_out;

    repack_w_kernel<<<NKSG * 32 * 32 / 256, 256>>>(weight);
    sim_stats_kernel<<<dim3(T_ / 64, B_), 256>>>(embedding);
    sim_finalize_kernel<<<(B_ * T_ + 255) / 256, 256>>>();
    attconv_gemm_mma<<<dim3(T_ / BN, O_ / BM, B_), THREADS, SMEM_U32 * 4>>>(
        feature, out);
}

// round 5
// speedup vs baseline: 4.9123x; 1.3842x over previous
#include <cuda_runtime.h>
#include <cuda_fp16.h>
#include <math.h>
#include <cstdint>

// Problem constants
#define B_  8
#define C_  512
#define T_  4096
#define O_  512
#define CK_ 1536
#define EPS 1e-8f

// GEMM tiling
#define BM 128
#define BN 128
#define BK 32
#define NKT (CK_ / BK)        // 48 k-tiles
#define NKS16 (CK_ / 16)      // 96 global k16-steps
#define THREADS 256

// SMEM (u32 units): scales + 2-stage fragment-order fp16 B tile
// B tile: 2 ks16 * 16 n8 * 32 lanes * 2 u32 = 2048 u32 per stage
#define BTILE_U32 2048
#define OFF_SS    0
#define OFF_B     384
#define SMEM_U32  (384 + 2 * BTILE_U32)   // 4480 u32 = 17920 B

// Scratch
__device__ float g_n2[B_ * T_];
__device__ float g_d [B_ * T_];
__device__ float g_s [B_ * 3 * T_];
__device__ uint4 g_wf[NKS16 * 32 * 32];   // W repacked: fp16 m16n8k16 A frags

__device__ __forceinline__ uint32_t packh2(float a, float b) {
    __half2 h = __floats2half2_rn(a, b);
    return *reinterpret_cast<uint32_t*>(&h);
}

__device__ __forceinline__ void mma_16816(float* d, const uint32_t* a,
                                          const uint32_t* b) {
    asm volatile(
        "mma.sync.aligned.m16n8k16.row.col.f32.f16.f16.f32 "
        "{%0,%1,%2,%3}, {%4,%5,%6,%7}, {%8,%9}, {%0,%1,%2,%3};"
        : "+f"(d[0]), "+f"(d[1]), "+f"(d[2]), "+f"(d[3])
        : "r"(a[0]), "r"(a[1]), "r"(a[2]), "r"(a[3]), "r"(b[0]), "r"(b[1]));
}

// ---------------------------------------------------------------------------
// Kernel 0: repack W [O, CK] -> fp16 fragment-major (m16n8k16 A layout).
// uint4 index: (ks16*32 + m16)*32 + lane
//   x: {W[r, k0],   W[r, k0+1]}      r = m16*16 + lane/4
//   y: {W[r+8, k0], W[r+8, k0+1]}    k0 = ks16*16 + (lane%4)*2
//   z: {W[r, k0+8], W[r, k0+9]}
//   w: {W[r+8,k0+8],W[r+8,k0+9]}
// ---------------------------------------------------------------------------
__global__ void repack_w_kernel(const float* __restrict__ w) {
    const int idx  = blockIdx.x * 256 + threadIdx.x;   // 0 .. 96*32*32-1
    const int lane = idx & 31;
    const int m16  = (idx >> 5) & 31;
    const int ks   = idx >> 10;
    const int r    = m16 * 16 + (lane >> 2);
    const int k0   = ks * 16 + (lane & 3) * 2;
    const float* p0 = w + (size_t)r * CK_ + k0;
    const float* p1 = p0 + 8 * CK_;
    uint4 v;
    v.x = packh2(p0[0], p0[1]);
    v.y = packh2(p1[0], p1[1]);
    v.z = packh2(p0[8], p0[9]);
    v.w = packh2(p1[8], p1[9]);
    g_wf[idx] = v;
}

// ---------------------------------------------------------------------------
// Kernel 1: column stats. grid (T/32, B), block 256, C split 8-way.
// ---------------------------------------------------------------------------
__global__ void sim_stats_kernel(const float* __restrict__ emb) {
    const int tsub = threadIdx.x & 31;
    const int cp   = threadIdx.x >> 5;          // 0..7
    const int t    = blockIdx.x * 32 + tsub;
    const int b    = blockIdx.y;
    const float* e = emb + (size_t)b * C_ * T_ + (size_t)cp * 64 * T_ + t;

    float n2 = 0.f, dd = 0.f;
    if (t > 0) {
        #pragma unroll 4
        for (int c = 0; c < 64; ++c) {
            float v  = e[(size_t)c * T_];
            float vp = e[(size_t)c * T_ - 1];
            n2 = fmaf(v, v,  n2);
            dd = fmaf(v, vp, dd);
        }
    } else {
        #pragma unroll 4
        for (int c = 0; c < 64; ++c) {
            float v = e[(size_t)c * T_];
            n2 = fmaf(v, v, n2);
        }
    }
    __shared__ float sn[8][32], sd[8][32];
    sn[cp][tsub] = n2;
    sd[cp][tsub] = dd;
    __syncthreads();
    if (threadIdx.x < 32) {
        float a = 0.f, bsum = 0.f;
        #pragma unroll
        for (int j = 0; j < 8; ++j) { a += sn[j][tsub]; bsum += sd[j][tsub]; }
        g_n2[b * T_ + t] = a;
        g_d [b * T_ + t] = bsum;
    }
}

// ---------------------------------------------------------------------------
// Kernel 2: finalize cosine sims (torch eps semantics).
// ---------------------------------------------------------------------------
__global__ void sim_finalize_kernel() {
    const int idx = blockIdx.x * 256 + threadIdx.x;
    if (idx >= B_ * T_) return;
    const int b = idx / T_;
    const int t = idx - b * T_;
    const float* n2 = g_n2 + b * T_;
    const float* d  = g_d  + b * T_;

    float nm    = fmaxf(sqrtf(n2[t]), EPS);
    float nprev = (t > 0)      ? fmaxf(sqrtf(n2[t - 1]), EPS) : EPS;
    float nnext = (t < T_ - 1) ? fmaxf(sqrtf(n2[t + 1]), EPS) : EPS;

    float* s = g_s + (size_t)b * 3 * T_;
    s[0 * T_ + t] = d[t] / (nm * nprev);
    s[1 * T_ + t] = n2[t] / (nm * nm);
    s[2 * T_ + t] = ((t < T_ - 1) ? d[t + 1] : 0.f) / (nm * nnext);
}

// ---------------------------------------------------------------------------
// Kernel 3: fp16 m16n8k16 GEMM. A frags from repacked global; B (im2col*scale)
// built in SMEM directly in fragment order:
//   slot(ks16, n8, lane) = ((ks16*16 + n8)*32 + lane)*2 + {b0, b1}
//   lane = (col%8)*4 + q;  b0 holds k = 2q,2q+1;  b1 holds k = 8+2q, 9+2q
// ---------------------------------------------------------------------------
__global__ __launch_bounds__(THREADS, 2)
void attconv_gemm_mma(const float* __restrict__ feat,
                      float* __restrict__ out) {
    extern __shared__ uint32_t smem[];
    float*    sS  = (float*)(smem + OFF_SS);
    uint32_t* smB = smem + OFF_B;

    const int tid  = threadIdx.x;
    const int wid  = tid >> 5;
    const int lane = tid & 31;
    const int wm   = wid & 3;             // warp m index -> 32 rows
    const int wn   = wid >> 2;            // warp n index -> 64 cols
    const int b     = blockIdx.z;
    const int mBase = blockIdx.y * BM;
    const int nBase = blockIdx.x * BN;

    const float* fb   = feat + (size_t)b * C_ * T_;
    float*       outb = out  + (size_t)b * O_ * T_;

    // scale preload
    {
        const float* sbase = g_s + (size_t)b * 3 * T_;
        for (int i = tid; i < 3 * BN; i += THREADS) {
            int g = i >> 7, col = i & (BN - 1);
            sS[g * BN + col] = sbase[g * T_ + nBase + col];
        }
    }
    __syncthreads();

    // B builder mapping: thread -> (column, k-half of 16)
    const int bCol  = tid & 127;
    const int kHalf = tid >> 7;            // 0/1 -> ks16 within tile
    const float sc0 = sS[0 * BN + bCol];
    const float sc1 = sS[1 * BN + bCol];
    const float sc2 = sS[2 * BN + bCol];

    float xv[16];
    auto loadB = [&](int iBase) {
        const int g = iBase >> 9;
        const float sg = (g == 0) ? sc0 : (g == 1) ? sc1 : sc2;
        const int i0 = iBase + kHalf * 16;
        #pragma unroll
        for (int kk = 0; kk < 16; ++kk) {
            int i  = i0 + kk;
            int c  = i / 3;
            int k3 = i - 3 * c;
            int t  = nBase + bCol + k3 - 1;
            float v = ((unsigned)t < (unsigned)T_) ? __ldg(&fb[(size_t)c * T_ + t]) : 0.f;
            xv[kk] = v * sg;
        }
    };
    const int n8    = bCol >> 3;
    const uint32_t sBase = ((kHalf * 16 + n8) * 32 + (bCol & 7) * 4) * 2;
    auto storeB = [&](int stage) {
        uint32_t* d = smB + stage * BTILE_U32 + sBase;
        *reinterpret_cast<uint4*>(d) = make_uint4(
            packh2(xv[0], xv[1]),  packh2(xv[8],  xv[9]),
            packh2(xv[2], xv[3]),  packh2(xv[10], xv[11]));
        *reinterpret_cast<uint4*>(d + 4) = make_uint4(
            packh2(xv[4], xv[5]),  packh2(xv[12], xv[13]),
            packh2(xv[6], xv[7]),  packh2(xv[14], xv[15]));
    };

    float acc[2][8][4] = {};
    // A fragment base: g_wf[(ks16*32 + m16)*32 + lane]
    const int m16base = (mBase >> 4) + wm * 2;
    const uint4* aW = g_wf + (size_t)m16base * 32 + lane;

    auto compute = [&](int stage, int kt) {
        const uint32_t* bp = smB + stage * BTILE_U32 + (wn * 8) * 32 * 2 + lane * 2;
        #pragma unroll
        for (int ks = 0; ks < 2; ++ks) {
            const size_t ksg = (size_t)(kt * 2 + ks);
            uint4 a0 = __ldg(aW + (ksg * 32 + 0) * 32);
            uint4 a1 = __ldg(aW + (ksg * 32 + 1) * 32);
            uint32_t af[2][4] = {{a0.x, a0.y, a0.z, a0.w},
                                 {a1.x, a1.y, a1.z, a1.w}};
            uint32_t bf[8][2];
            #pragma unroll
            for (int ni = 0; ni < 8; ++ni) {
                uint2 v = *reinterpret_cast<const uint2*>(
                    bp + (ks * 16 + ni) * 64);
                bf[ni][0] = v.x;
                bf[ni][1] = v.y;
            }
            #pragma unroll
            for (int mi = 0; mi < 2; ++mi)
                #pragma unroll
                for (int ni = 0; ni < 8; ++ni)
                    mma_16816(acc[mi][ni], af[mi], bf[ni]);
        }
    };

    // prologue
    loadB(0);
    storeB(0);
    __syncthreads();

    for (int kt = 0; kt < NKT; ++kt) {
        const int cur = kt & 1;
        if (kt + 1 < NKT) loadB((kt + 1) * BK);
        compute(cur, kt);
        if (kt + 1 < NKT) storeB(cur ^ 1);
        __syncthreads();
    }

    // epilogue: direct float2 stores
    const int rBase = mBase + wm * 32 + (lane >> 2);
    const int cBase = nBase + wn * 64 + (lane & 3) * 2;
    #pragma unroll
    for (int mi = 0; mi < 2; ++mi) {
        #pragma unroll
        for (int ni = 0; ni < 8; ++ni) {
            const int row = rBase + mi * 16;
            const int col = cBase + ni * 8;
            float2 v0 = make_float2(acc[mi][ni][0], acc[mi][ni][1]);
            float2 v1 = make_float2(acc[mi][ni][2], acc[mi][ni][3]);
            *reinterpret_cast<float2*>(&outb[(size_t)row * T_ + col])       = v0;
            *reinterpret_cast<float2*>(&outb[(size_t)(row + 8) * T_ + col]) = v1;
        }
    }
}

// ---------------------------------------------------------------------------
// Launch: inputs in metadata order: feature, embedding, weight
// ---------------------------------------------------------------------------
extern "C" void kernel_launch(void* const* d_in, const int* in_sizes, int n_in,
                              void* d_out, int out_size) {
    const float* feature   = (const float*)d_in[0];
    const float* embedding = (const float*)d_in[1];
    const float* weight    = (const float*)d_in[2];
    float* out = (float*)d_out;

    repack_w_kernel<<<NKS16 * 32 * 32 / 256, 256>>>(weight);
    sim_stats_kernel<<<dim3(T_ / 32, B_), 256>>>(embedding);
    sim_finalize_kernel<<<(B_ * T_ + 255) / 256, 256>>>();
    attconv_gemm_mma<<<dim3(T_ / BN, O_ / BM, B_), THREADS, SMEM_U32 * 4>>>(
        feature, out);
}

// round 6
// speedup vs baseline: 6.6205x; 1.3477x over previous
#include <cuda_runtime.h>
#include <cuda_fp16.h>
#include <math.h>
#include <cstdint>

// Problem constants
#define B_  8
#define C_  512
#define T_  4096
#define O_  512
#define CK_ 1536
#define EPS 1e-8f

#define NKS16 (CK_ / 16)      // 96 k16-steps
#define NKP   (CK_ / 32)      // 48 k32-steps (ks16 pairs)
#define NT8   (T_ / 8)        // 512 n8 columns

// Scratch
__device__ float g_n2[B_ * T_];
__device__ float g_d [B_ * T_];
__device__ float g_s [B_ * 3 * T_];
__device__ uint4 g_wf[NKS16 * 32 * 32];             // W fp16 A-frags
__device__ uint4 g_xf[(size_t)B_ * NT8 * NKP * 32]; // Xs fp16 B-frags (~100MB)

__device__ __forceinline__ uint32_t packh2(float a, float b) {
    __half2 h = __floats2half2_rn(a, b);
    return *reinterpret_cast<uint32_t*>(&h);
}

__device__ __forceinline__ void mma_16816(float* d, const uint32_t* a,
                                          uint32_t b0, uint32_t b1) {
    asm volatile(
        "mma.sync.aligned.m16n8k16.row.col.f32.f16.f16.f32 "
        "{%0,%1,%2,%3}, {%4,%5,%6,%7}, {%8,%9}, {%0,%1,%2,%3};"
        : "+f"(d[0]), "+f"(d[1]), "+f"(d[2]), "+f"(d[3])
        : "r"(a[0]), "r"(a[1]), "r"(a[2]), "r"(a[3]), "r"(b0), "r"(b1));
}

// ---------------------------------------------------------------------------
// Kernel 0: repack W [O, CK] -> fp16 A-fragment order (unchanged from R5).
// ---------------------------------------------------------------------------
__global__ void repack_w_kernel(const float* __restrict__ w) {
    const int idx  = blockIdx.x * 256 + threadIdx.x;
    const int lane = idx & 31;
    const int m16  = (idx >> 5) & 31;
    const int ks   = idx >> 10;
    const int r    = m16 * 16 + (lane >> 2);
    const int k0   = ks * 16 + (lane & 3) * 2;
    const float* p0 = w + (size_t)r * CK_ + k0;
    const float* p1 = p0 + 8 * CK_;
    uint4 v;
    v.x = packh2(p0[0], p0[1]);
    v.y = packh2(p1[0], p1[1]);
    v.z = packh2(p0[8], p0[9]);
    v.w = packh2(p1[8], p1[9]);
    g_wf[idx] = v;
}

// ---------------------------------------------------------------------------
// Kernel 1: column stats. grid (T/32, B), block 256, C split 8-way.
// ---------------------------------------------------------------------------
__global__ void sim_stats_kernel(const float* __restrict__ emb) {
    const int tsub = threadIdx.x & 31;
    const int cp   = threadIdx.x >> 5;
    const int t    = blockIdx.x * 32 + tsub;
    const int b    = blockIdx.y;
    const float* e = emb + (size_t)b * C_ * T_ + (size_t)cp * 64 * T_ + t;

    float n2 = 0.f, dd = 0.f;
    if (t > 0) {
        #pragma unroll 4
        for (int c = 0; c < 64; ++c) {
            float v  = e[(size_t)c * T_];
            float vp = e[(size_t)c * T_ - 1];
            n2 = fmaf(v, v,  n2);
            dd = fmaf(v, vp, dd);
        }
    } else {
        #pragma unroll 4
        for (int c = 0; c < 64; ++c) {
            float v = e[(size_t)c * T_];
            n2 = fmaf(v, v, n2);
        }
    }
    __shared__ float sn[8][32], sd[8][32];
    sn[cp][tsub] = n2;
    sd[cp][tsub] = dd;
    __syncthreads();
    if (threadIdx.x < 32) {
        float a = 0.f, bs = 0.f;
        #pragma unroll
        for (int j = 0; j < 8; ++j) { a += sn[j][tsub]; bs += sd[j][tsub]; }
        g_n2[b * T_ + t] = a;
        g_d [b * T_ + t] = bs;
    }
}

// ---------------------------------------------------------------------------
// Kernel 2: finalize cosine sims (torch eps semantics).
// ---------------------------------------------------------------------------
__global__ void sim_finalize_kernel() {
    const int idx = blockIdx.x * 256 + threadIdx.x;
    if (idx >= B_ * T_) return;
    const int b = idx / T_;
    const int t = idx - b * T_;
    const float* n2 = g_n2 + b * T_;
    const float* d  = g_d  + b * T_;

    float nm    = fmaxf(sqrtf(n2[t]), EPS);
    float nprev = (t > 0)      ? fmaxf(sqrtf(n2[t - 1]), EPS) : EPS;
    float nnext = (t < T_ - 1) ? fmaxf(sqrtf(n2[t + 1]), EPS) : EPS;

    float* s = g_s + (size_t)b * 3 * T_;
    s[0 * T_ + t] = d[t] / (nm * nprev);
    s[1 * T_ + t] = n2[t] / (nm * nm);
    s[2 * T_ + t] = ((t < T_ - 1) ? d[t + 1] : 0.f) / (nm * nnext);
}

// ---------------------------------------------------------------------------
// Kernel 3: build Xs fragments.  One uint4 per (b, n8, kp, lane):
//   col = lane>>2 (t = n8*8+col), q = lane&3
//   x = {Xs[kp*32+2q, t],    Xs[kp*32+2q+1, t]}     (b0 of ks16=2kp)
//   y = {Xs[kp*32+8+2q, t],  Xs[kp*32+9+2q, t]}     (b1 of ks16=2kp)
//   z = {Xs[kp*32+16+2q, t], Xs[kp*32+17+2q, t]}    (b0 of ks16=2kp+1)
//   w = {Xs[kp*32+24+2q, t], Xs[kp*32+25+2q, t]}    (b1 of ks16=2kp+1)
// where Xs[i, t] = feat[b, i/3, t + i%3 - 1] * s[b, i>>9, t]
// grid (6, NT8, B), block 256: kp = bx*8 + tid>>5, coalesced 4KB stores/block.
// ---------------------------------------------------------------------------
__global__ __launch_bounds__(256)
void build_xs_kernel(const float* __restrict__ feat) {
    const int lane = threadIdx.x & 31;
    const int kp   = blockIdx.x * 8 + (threadIdx.x >> 5);
    const int n8   = blockIdx.y;
    const int b    = blockIdx.z;
    const int col  = lane >> 2;
    const int q    = lane & 3;
    const int t    = n8 * 8 + col;

    const float* fb = feat + (size_t)b * C_ * T_;
    const float  sg = g_s[(size_t)b * 3 * T_ + (kp >> 4) * T_ + t];

    float x[8];
    #pragma unroll
    for (int j = 0; j < 8; ++j) {
        const int off = (j >> 1) * 8 + 2 * q + (j & 1);
        const int i   = kp * 32 + off;
        const int c   = i / 3;
        const int k3  = i - 3 * c;
        const int tt  = t + k3 - 1;
        float v = ((unsigned)tt < (unsigned)T_) ? __ldg(&fb[(size_t)c * T_ + tt]) : 0.f;
        x[j] = v * sg;
    }
    uint4 v;
    v.x = packh2(x[0], x[1]);
    v.y = packh2(x[2], x[3]);
    v.z = packh2(x[4], x[5]);
    v.w = packh2(x[6], x[7]);
    g_xf[(((size_t)b * NT8 + n8) * NKP + kp) * 32 + lane] = v;
}

// ---------------------------------------------------------------------------
// Kernel 4: pure-MMA GEMM. No SMEM, no syncs. Warp tile 64(M) x 32(N).
// grid (16, 8, 8): x = n-group (8 warps x 4 n8), y = m-tile (4 m16), z = batch.
// ---------------------------------------------------------------------------
__global__ __launch_bounds__(256, 2)
void attconv_gemm_mma(float* __restrict__ out) {
    const int tid  = threadIdx.x;
    const int wid  = tid >> 5;
    const int lane = tid & 31;
    const int b       = blockIdx.z;
    const int m16Base = blockIdx.y * 4;
    const int n8Base  = blockIdx.x * 32 + wid * 4;

    const uint4* aW = g_wf + lane;
    const uint4* xB = g_xf + (((size_t)b * NT8 + n8Base) * NKP) * 32 + lane;

    float acc[4][4][4] = {};

    for (int kp = 0; kp < NKP; ++kp) {
        uint4 bv[4];
        #pragma unroll
        for (int ni = 0; ni < 4; ++ni)
            bv[ni] = __ldg(xB + ((size_t)ni * NKP + kp) * 32);

        #pragma unroll
        for (int ks = 0; ks < 2; ++ks) {
            const int ksg = 2 * kp + ks;
            uint32_t af[4][4];
            #pragma unroll
            for (int mi = 0; mi < 4; ++mi) {
                uint4 a = __ldg(aW + (size_t)((ksg * 32 + m16Base + mi) << 5));
                af[mi][0] = a.x; af[mi][1] = a.y; af[mi][2] = a.z; af[mi][3] = a.w;
            }
            #pragma unroll
            for (int mi = 0; mi < 4; ++mi)
                #pragma unroll
                for (int ni = 0; ni < 4; ++ni) {
                    const uint32_t b0 = ks ? bv[ni].z : bv[ni].x;
                    const uint32_t b1 = ks ? bv[ni].w : bv[ni].y;
                    mma_16816(acc[mi][ni], af[mi], b0, b1);
                }
        }
    }

    // epilogue: direct float2 stores
    float* outb = out + (size_t)b * O_ * T_;
    #pragma unroll
    for (int mi = 0; mi < 4; ++mi) {
        const int row0 = (m16Base + mi) * 16 + (lane >> 2);
        #pragma unroll
        for (int ni = 0; ni < 4; ++ni) {
            const int col = (n8Base + ni) * 8 + (lane & 3) * 2;
            float2 v0 = make_float2(acc[mi][ni][0], acc[mi][ni][1]);
            float2 v1 = make_float2(acc[mi][ni][2], acc[mi][ni][3]);
            *reinterpret_cast<float2*>(&outb[(size_t)row0 * T_ + col])       = v0;
            *reinterpret_cast<float2*>(&outb[(size_t)(row0 + 8) * T_ + col]) = v1;
        }
    }
}

// ---------------------------------------------------------------------------
// Launch: inputs in metadata order: feature, embedding, weight
// ---------------------------------------------------------------------------
extern "C" void kernel_launch(void* const* d_in, const int* in_sizes, int n_in,
                              void* d_out, int out_size) {
    const float* feature   = (const float*)d_in[0];
    const float* embedding = (const float*)d_in[1];
    const float* weight    = (const float*)d_in[2];
    float* out = (float*)d_out;

    repack_w_kernel<<<NKS16 * 32 * 32 / 256, 256>>>(weight);
    sim_stats_kernel<<<dim3(T_ / 32, B_), 256>>>(embedding);
    sim_finalize_kernel<<<(B_ * T_ + 255) / 256, 256>>>();
    build_xs_kernel<<<dim3(NKP / 8, NT8, B_), 256>>>(feature);
    attconv_gemm_mma<<<dim3(16, 8, B_), 256>>>(out);
}